// round 3
// baseline (speedup 1.0000x reference)
#include <cuda_runtime.h>
#include <cuda_bf16.h>
#include <math.h>

#define N_NODES 100000
#define N_EDGES 640000
#define F_IN 128
#define HID 128
#define N_CLS 40

// ---------------- device scratch (no allocations allowed) ----------------
__device__ float g_t[N_NODES * HID];    // GEMM output (pre-aggregation)
__device__ float g_a[N_NODES * HID];    // aggregation output
__device__ int   g_cnt[N_NODES];        // in-degree (edges only)
__device__ int   g_fill[N_NODES];       // CSR fill cursor
__device__ float g_dinv[N_NODES];       // deg^{-1/2} (deg includes self-loop)
__device__ int   g_rowptr[N_NODES + 1];
__device__ int   g_eidx[N_EDGES];       // src node per CSR-sorted edge
__device__ float g_enorm[N_EDGES];      // dinv[src]*dinv[dst] per CSR-sorted edge

// ---------------- prep kernels ----------------
__global__ void k_zero() {
    int i = blockIdx.x * blockDim.x + threadIdx.x;
    if (i < N_NODES) { g_cnt[i] = 0; g_fill[i] = 0; }
}

__global__ void k_count(const int* __restrict__ dst) {
    int e = blockIdx.x * blockDim.x + threadIdx.x;
    if (e < N_EDGES) atomicAdd(&g_cnt[dst[e]], 1);
}

__global__ void k_dinv() {
    int i = blockIdx.x * blockDim.x + threadIdx.x;
    if (i < N_NODES) g_dinv[i] = rsqrtf((float)(g_cnt[i] + 1));  // +1 self-loop
}

// Single-block exclusive scan of g_cnt -> g_rowptr (N_NODES entries + total)
__global__ void k_scan() {
    __shared__ int sh[1024];
    __shared__ int carry_s;
    int tid = threadIdx.x;
    if (tid == 0) carry_s = 0;
    __syncthreads();
    for (int base = 0; base < N_NODES; base += 1024) {
        int i = base + tid;
        int v = (i < N_NODES) ? g_cnt[i] : 0;
        sh[tid] = v;
        __syncthreads();
        // Hillis-Steele inclusive scan
        #pragma unroll
        for (int off = 1; off < 1024; off <<= 1) {
            int t = (tid >= off) ? sh[tid - off] : 0;
            __syncthreads();
            sh[tid] += t;
            __syncthreads();
        }
        if (i < N_NODES) g_rowptr[i] = carry_s + sh[tid] - v;  // exclusive
        __syncthreads();
        if (tid == 1023) carry_s += sh[1023];
        __syncthreads();
    }
    if (tid == 0) g_rowptr[N_NODES] = carry_s;
}

__global__ void k_scatter(const int* __restrict__ src, const int* __restrict__ dst) {
    int e = blockIdx.x * blockDim.x + threadIdx.x;
    if (e >= N_EDGES) return;
    int s = src[e], d = dst[e];
    int pos = g_rowptr[d] + atomicAdd(&g_fill[d], 1);
    g_eidx[pos] = s;
    g_enorm[pos] = g_dinv[s] * g_dinv[d];
}

// ---------------- GEMM [n,128] x [128,128] ----------------
// 256 threads, 64 rows x 128 cols per block, K-tile 32.
__global__ __launch_bounds__(256) void gemm128(
    const float* __restrict__ A, const float* __restrict__ W,
    float* __restrict__ out, int n)
{
    __shared__ float As[64][32];
    __shared__ float Ws[32][128];
    int tid = threadIdx.x;
    int tx = tid & 31;       // col group: cols tx*4..tx*4+3
    int ty = tid >> 5;       // row group: rows ty*8..ty*8+7
    int r0 = blockIdx.x * 64;

    float acc[8][4];
    #pragma unroll
    for (int i = 0; i < 8; i++)
        #pragma unroll
        for (int j = 0; j < 4; j++) acc[i][j] = 0.f;

    for (int k0 = 0; k0 < 128; k0 += 32) {
        // load A tile: 64 rows x 32 cols = 512 float4
        #pragma unroll
        for (int l = 0; l < 2; l++) {
            int idx = tid + l * 256;
            int row = idx >> 3, f = idx & 7;
            int gr = r0 + row;
            float4 v = make_float4(0.f, 0.f, 0.f, 0.f);
            if (gr < n) v = *(const float4*)&A[gr * 128 + k0 + f * 4];
            *(float4*)&As[row][f * 4] = v;
        }
        // load W tile: 32 rows x 128 cols = 1024 float4
        #pragma unroll
        for (int l = 0; l < 4; l++) {
            int idx = tid + l * 256;
            int row = idx >> 5, f = idx & 31;
            *(float4*)&Ws[row][f * 4] = *(const float4*)&W[(k0 + row) * 128 + f * 4];
        }
        __syncthreads();
        #pragma unroll
        for (int k = 0; k < 32; k++) {
            float4 bv = *(const float4*)&Ws[k][tx * 4];
            #pragma unroll
            for (int i = 0; i < 8; i++) {
                float a = As[ty * 8 + i][k];
                acc[i][0] += a * bv.x;
                acc[i][1] += a * bv.y;
                acc[i][2] += a * bv.z;
                acc[i][3] += a * bv.w;
            }
        }
        __syncthreads();
    }
    #pragma unroll
    for (int i = 0; i < 8; i++) {
        int gr = r0 + ty * 8 + i;
        if (gr < n) {
            float4 v = make_float4(acc[i][0], acc[i][1], acc[i][2], acc[i][3]);
            *(float4*)&out[gr * 128 + tx * 4] = v;
        }
    }
}

// ---------------- GEMM [n,128] x [128,40] ----------------
// 320 threads, 32 rows per block, full K in smem.
__global__ __launch_bounds__(320) void gemm40(
    const float* __restrict__ A, const float* __restrict__ W,
    float* __restrict__ out, int n)
{
    __shared__ float As[32][128];
    __shared__ float Ws[128 * 40];
    int tid = threadIdx.x;            // 0..319
    int tx = tid % 40;                // col
    int ty = tid / 40;                // 0..7 -> rows ty*4..ty*4+3
    int r0 = blockIdx.x * 32;

    for (int idx = tid; idx < 32 * 32; idx += 320) {  // 1024 float4
        int row = idx >> 5, f = idx & 31;
        int gr = r0 + row;
        float4 v = make_float4(0.f, 0.f, 0.f, 0.f);
        if (gr < n) v = *(const float4*)&A[gr * 128 + f * 4];
        *(float4*)&As[row][f * 4] = v;
    }
    for (int idx = tid; idx < 128 * 40; idx += 320) Ws[idx] = W[idx];
    __syncthreads();

    float acc[4] = {0.f, 0.f, 0.f, 0.f};
    #pragma unroll 8
    for (int k = 0; k < 128; k++) {
        float b = Ws[k * 40 + tx];
        #pragma unroll
        for (int i = 0; i < 4; i++) acc[i] += As[ty * 4 + i][k] * b;
    }
    #pragma unroll
    for (int i = 0; i < 4; i++) {
        int gr = r0 + ty * 4 + i;
        if (gr < n) out[gr * 40 + tx] = acc[i];
    }
}

// ---------------- aggregation: warp per node, H=128 (float4 lanes) ----------------
__global__ __launch_bounds__(256) void agg128(
    const float* __restrict__ t, const float* __restrict__ bias,
    float* __restrict__ out, int do_relu)
{
    int warp = (blockIdx.x * blockDim.x + threadIdx.x) >> 5;
    if (warp >= N_NODES) return;
    int lane = threadIdx.x & 31;
    const float4* t4 = (const float4*)t;

    float dv = g_dinv[warp];
    float self = dv * dv;
    float4 v = t4[warp * 32 + lane];
    float ax = self * v.x, ay = self * v.y, az = self * v.z, aw = self * v.w;

    int e0 = g_rowptr[warp], e1 = g_rowptr[warp + 1];
    for (int e = e0; e < e1; e++) {
        int s = g_eidx[e];
        float w = g_enorm[e];
        float4 u = t4[s * 32 + lane];
        ax += w * u.x; ay += w * u.y; az += w * u.z; aw += w * u.w;
    }
    float4 bb = ((const float4*)bias)[lane];
    ax += bb.x; ay += bb.y; az += bb.z; aw += bb.w;
    if (do_relu) {
        ax = fmaxf(ax, 0.f); ay = fmaxf(ay, 0.f);
        az = fmaxf(az, 0.f); aw = fmaxf(aw, 0.f);
    }
    float4 r = make_float4(ax, ay, az, aw);
    ((float4*)out)[warp * 32 + lane] = r;
}

// ---------------- final aggregation (H=40) fused with log_softmax ----------------
__global__ __launch_bounds__(256) void agg40_lsm(
    const float* __restrict__ t, const float* __restrict__ bias,
    float* __restrict__ out)
{
    int warp = (blockIdx.x * blockDim.x + threadIdx.x) >> 5;
    if (warp >= N_NODES) return;
    int lane = threadIdx.x & 31;

    float dv = g_dinv[warp];
    float self = dv * dv;
    bool hi = (lane < 8);
    float a0 = self * t[warp * 40 + lane];
    float a1 = hi ? self * t[warp * 40 + 32 + lane] : 0.f;

    int e0 = g_rowptr[warp], e1 = g_rowptr[warp + 1];
    for (int e = e0; e < e1; e++) {
        int s = g_eidx[e];
        float w = g_enorm[e];
        a0 += w * t[s * 40 + lane];
        if (hi) a1 += w * t[s * 40 + 32 + lane];
    }
    a0 += bias[lane];
    if (hi) a1 += bias[32 + lane];

    // log_softmax over 40 values held across the warp
    float m = fmaxf(a0, hi ? a1 : -INFINITY);
    #pragma unroll
    for (int off = 16; off > 0; off >>= 1)
        m = fmaxf(m, __shfl_xor_sync(0xFFFFFFFFu, m, off));
    float s = expf(a0 - m) + (hi ? expf(a1 - m) : 0.f);
    #pragma unroll
    for (int off = 16; off > 0; off >>= 1)
        s += __shfl_xor_sync(0xFFFFFFFFu, s, off);
    float l = m + logf(s);

    out[warp * 40 + lane] = a0 - l;
    if (hi) out[warp * 40 + 32 + lane] = a1 - l;
}

// ---------------- launch ----------------
extern "C" void kernel_launch(void* const* d_in, const int* in_sizes, int n_in,
                              void* d_out, int out_size)
{
    const float* x  = (const float*)d_in[0];
    const int*   ei = (const int*)d_in[1];
    const float* W1 = (const float*)d_in[2];
    const float* b1 = (const float*)d_in[3];
    const float* W2 = (const float*)d_in[4];
    const float* b2 = (const float*)d_in[5];
    const float* W3 = (const float*)d_in[6];
    const float* b3 = (const float*)d_in[7];
    const float* W4 = (const float*)d_in[8];
    const float* b4 = (const float*)d_in[9];
    float* out = (float*)d_out;

    const int* src = ei;
    const int* dst = ei + N_EDGES;

    float* t;  cudaGetSymbolAddress((void**)&t,  g_t);
    float* a;  cudaGetSymbolAddress((void**)&a,  g_a);

    const int NB_N = (N_NODES + 255) / 256;   // 391
    const int NB_E = (N_EDGES + 255) / 256;   // 2500
    const int NB_G = (N_NODES + 63) / 64;     // 1563
    const int NB_G40 = (N_NODES + 31) / 32;   // 3125
    const int NB_W = (N_NODES * 32 + 255) / 256; // 12500

    // graph structure prep
    k_zero<<<NB_N, 256>>>();
    k_count<<<NB_E, 256>>>(dst);
    k_dinv<<<NB_N, 256>>>();
    k_scan<<<1, 1024>>>();
    k_scatter<<<NB_E, 256>>>(src, dst);

    // layer 1
    gemm128<<<NB_G, 256>>>(x, W1, t, N_NODES);
    agg128<<<NB_W, 256>>>(t, b1, a, 1);
    // layer 2
    gemm128<<<NB_G, 256>>>(a, W2, t, N_NODES);
    agg128<<<NB_W, 256>>>(t, b2, a, 1);
    // layer 3
    gemm128<<<NB_G, 256>>>(a, W3, t, N_NODES);
    agg128<<<NB_W, 256>>>(t, b3, a, 1);
    // layer 4 + log_softmax
    gemm40<<<NB_G40, 320>>>(a, W4, t, N_NODES);
    agg40_lsm<<<NB_W, 256>>>(t, b4, out);
}

// round 6
// speedup vs baseline: 1.5218x; 1.5218x over previous
#include <cuda_runtime.h>
#include <cuda_bf16.h>
#include <math.h>
#include <stdint.h>

#define N_NODES 100000
#define N_EDGES 640000

// ---------------- device scratch ----------------
__device__ float g_t[N_NODES * 128];            // GEMM output (pre-aggregation)
__device__ __nv_bfloat16 g_hi[N_NODES * 128];   // activation hi
__device__ __nv_bfloat16 g_lo[N_NODES * 128];   // activation lo
__device__ int   g_cnt[N_NODES];
__device__ int   g_fill[N_NODES];
__device__ float g_dinv[N_NODES];
__device__ int   g_rowptr[N_NODES + 1];
__device__ int   g_bsum[128];
__device__ int   g_eidx[N_EDGES];
__device__ float g_enorm[N_EDGES];
__device__ __nv_bfloat16 g_whi[3 * 128 * 128];  // W1..W3 transposed hi  [n][k]
__device__ __nv_bfloat16 g_wlo[3 * 128 * 128];  // W1..W3 transposed lo  [n][k]

__device__ __forceinline__ uint32_t s2u(const void* p) {
    uint32_t a;
    asm("{ .reg .u64 t; cvta.to.shared.u64 t, %1; cvt.u32.u64 %0, t; }" : "=r"(a) : "l"(p));
    return a;
}

// ---------------- prep kernels ----------------
__global__ void k_zero() {
    int i = blockIdx.x * blockDim.x + threadIdx.x;
    if (i < N_NODES) { g_cnt[i] = 0; g_fill[i] = 0; }
}
__global__ void k_count(const int* __restrict__ dst) {
    int e = blockIdx.x * blockDim.x + threadIdx.x;
    if (e < N_EDGES) atomicAdd(&g_cnt[dst[e]], 1);
}
__global__ void k_dinv() {
    int i = blockIdx.x * blockDim.x + threadIdx.x;
    if (i < N_NODES) g_dinv[i] = rsqrtf((float)(g_cnt[i] + 1));
}

// multi-block scan: phase 1 (per-1024-block scan, block sums out)
__global__ __launch_bounds__(1024) void k_scan1() {
    int tid = threadIdx.x;
    int i = blockIdx.x * 1024 + tid;
    int v = (i < N_NODES) ? g_cnt[i] : 0;
    int lane = tid & 31, w = tid >> 5;
    int x = v;
    #pragma unroll
    for (int off = 1; off < 32; off <<= 1) {
        int t = __shfl_up_sync(0xFFFFFFFFu, x, off);
        if (lane >= off) x += t;
    }
    __shared__ int ws[32];
    if (lane == 31) ws[w] = x;
    __syncthreads();
    if (w == 0) {
        int y = ws[lane], o = y;
        #pragma unroll
        for (int off = 1; off < 32; off <<= 1) {
            int t = __shfl_up_sync(0xFFFFFFFFu, y, off);
            if (lane >= off) y += t;
        }
        ws[lane] = y - o;
    }
    __syncthreads();
    int incl = x + ws[w];
    if (i < N_NODES) g_rowptr[i] = incl - v;
    if (tid == 1023) g_bsum[blockIdx.x] = incl;
}
__global__ void k_scan2() {
    int tid = threadIdx.x;  // 128
    int v = (tid < 98) ? g_bsum[tid] : 0;
    int lane = tid & 31, w = tid >> 5;
    int x = v;
    #pragma unroll
    for (int off = 1; off < 32; off <<= 1) {
        int t = __shfl_up_sync(0xFFFFFFFFu, x, off);
        if (lane >= off) x += t;
    }
    __shared__ int ws[4];
    if (lane == 31) ws[w] = x;
    __syncthreads();
    __shared__ int wo[4];
    if (tid == 0) { int s = 0; for (int k = 0; k < 4; k++) { wo[k] = s; s += ws[k]; } }
    __syncthreads();
    if (tid < 98) g_bsum[tid] = x - v + wo[w];
}
__global__ void k_scan3() {
    int i = blockIdx.x * blockDim.x + threadIdx.x;
    if (i < N_NODES) g_rowptr[i] += g_bsum[i >> 10];
    if (i == 0) g_rowptr[N_NODES] = N_EDGES;
}
__global__ void k_scatter(const int* __restrict__ src, const int* __restrict__ dst) {
    int e = blockIdx.x * blockDim.x + threadIdx.x;
    if (e >= N_EDGES) return;
    int s = src[e], d = dst[e];
    int pos = g_rowptr[d] + atomicAdd(&g_fill[d], 1);
    g_eidx[pos] = s;
    g_enorm[pos] = g_dinv[s] * g_dinv[d];
}

// ---------------- precision-split conversion ----------------
__global__ void k_convx(const float* __restrict__ x) {
    int i = blockIdx.x * blockDim.x + threadIdx.x;
    if (i >= N_NODES * 32) return;
    float4 v = ((const float4*)x)[i];
    __nv_bfloat16 h0 = __float2bfloat16(v.x), h1 = __float2bfloat16(v.y);
    __nv_bfloat16 h2 = __float2bfloat16(v.z), h3 = __float2bfloat16(v.w);
    __nv_bfloat16 l0 = __float2bfloat16(v.x - __bfloat162float(h0));
    __nv_bfloat16 l1 = __float2bfloat16(v.y - __bfloat162float(h1));
    __nv_bfloat16 l2 = __float2bfloat16(v.z - __bfloat162float(h2));
    __nv_bfloat16 l3 = __float2bfloat16(v.w - __bfloat162float(h3));
    __nv_bfloat162* hp = (__nv_bfloat162*)g_hi;
    __nv_bfloat162* lp = (__nv_bfloat162*)g_lo;
    __nv_bfloat162 a; a.x = h0; a.y = h1; hp[i * 2] = a;
    __nv_bfloat162 b; b.x = h2; b.y = h3; hp[i * 2 + 1] = b;
    __nv_bfloat162 c; c.x = l0; c.y = l1; lp[i * 2] = c;
    __nv_bfloat162 d; d.x = l2; d.y = l3; lp[i * 2 + 1] = d;
}
// W [128k,128n] fp32 -> transposed [n][k] bf16 hi/lo
__global__ void k_convw(const float* __restrict__ W, __nv_bfloat16* __restrict__ hi,
                        __nv_bfloat16* __restrict__ lo) {
    int i = blockIdx.x * blockDim.x + threadIdx.x;  // 16384
    int n = i >> 7, k = i & 127;
    float v = W[k * 128 + n];
    __nv_bfloat16 h = __float2bfloat16(v);
    hi[i] = h;
    lo[i] = __float2bfloat16(v - __bfloat162float(h));
}

// ---------------- HMMA GEMM: [n,128]x[128,128] via bf16 hi/lo split ----------------
// smem tiles, row stride 136 bf16 (= 272 B) for conflict-free ldmatrix
#define TSTRIDE 272
#define SA_HI 0
#define SA_LO (SA_HI + 128 * TSTRIDE)
#define SW_HI (SA_LO + 128 * TSTRIDE)
#define SW_LO (SW_HI + 128 * TSTRIDE)
#define SM_TOTAL (SW_LO + 128 * TSTRIDE)   // 139264 B

#define LDSM_X4(r0, r1, r2, r3, addr) \
    asm volatile("ldmatrix.sync.aligned.m8n8.x4.shared.b16 {%0,%1,%2,%3}, [%4];" \
                 : "=r"(r0), "=r"(r1), "=r"(r2), "=r"(r3) : "r"(addr))

#define MMA16816(d, a, b0, b1) \
    asm volatile("mma.sync.aligned.m16n8k16.row.col.f32.bf16.bf16.f32 " \
                 "{%0,%1,%2,%3}, {%4,%5,%6,%7}, {%8,%9}, {%0,%1,%2,%3};" \
                 : "+f"((d)[0]), "+f"((d)[1]), "+f"((d)[2]), "+f"((d)[3]) \
                 : "r"((a)[0]), "r"((a)[1]), "r"((a)[2]), "r"((a)[3]), \
                   "r"(b0), "r"(b1))

__global__ __launch_bounds__(256) void gemm_mma(
    const __nv_bfloat16* __restrict__ Ahi, const __nv_bfloat16* __restrict__ Alo,
    const __nv_bfloat16* __restrict__ Whi, const __nv_bfloat16* __restrict__ Wlo,
    float* __restrict__ out, int n)
{
    extern __shared__ char smem[];
    const int tid = threadIdx.x;
    const int lane = tid & 31;
    const int wid = tid >> 5;
    const int wm = wid & 3;        // 4 M-groups of 32 rows
    const int wn = wid >> 2;       // 2 N-groups of 64 cols
    const int r0 = blockIdx.x * 128;

    // ---- fill smem: 4 tiles of 128 rows x 256 data bytes (stride 272) ----
    #pragma unroll
    for (int l = 0; l < 8; l++) {
        int chunk = tid + l * 256;             // 0..2047
        int r = chunk >> 4;
        int c = (chunk & 15) << 4;             // byte col within row (0..240)
        int so = r * TSTRIDE + c;
        int gr = r0 + r;
        uint4 va = make_uint4(0, 0, 0, 0), vb = make_uint4(0, 0, 0, 0);
        if (gr < n) {
            va = *(const uint4*)((const char*)Ahi + (size_t)gr * 256 + c);
            vb = *(const uint4*)((const char*)Alo + (size_t)gr * 256 + c);
        }
        *(uint4*)(smem + SA_HI + so) = va;
        *(uint4*)(smem + SA_LO + so) = vb;
        *(uint4*)(smem + SW_HI + so) = *(const uint4*)((const char*)Whi + (size_t)r * 256 + c);
        *(uint4*)(smem + SW_LO + so) = *(const uint4*)((const char*)Wlo + (size_t)r * 256 + c);
    }
    __syncthreads();

    const uint32_t sb = s2u(smem);

    // per-lane ldmatrix row/col offsets
    // A: lanes 0-7 rows+0 k0 | 8-15 rows+8 k0 | 16-23 rows+0 k+8 | 24-31 rows+8 k+8
    const int rA  = (lane & 7) + (((lane >> 3) & 1) << 3);
    const int kA8 = (lane >> 4) << 4;          // +16 bytes for k+8 half
    // B: lanes 0-7 n+0 k0 | 8-15 n+0 k+8 | 16-23 n+32 k0 | 24-31 n+32 k+8
    const int rBrow = (lane & 7) + ((lane >> 4) << 5);   // +32 rows for hi half
    const int kB8   = (((lane >> 3) & 1) << 4);          // +16 bytes for k+8

    const uint32_t aRow0 = (uint32_t)((wm * 32 + rA) * TSTRIDE + kA8);
    uint32_t bRow[4];
    #pragma unroll
    for (int j = 0; j < 4; j++)
        bRow[j] = (uint32_t)((wn * 64 + j * 8 + rBrow) * TSTRIDE + kB8);

    float acc[2][4][2][4];
    #pragma unroll
    for (int mt = 0; mt < 2; mt++)
        #pragma unroll
        for (int j = 0; j < 4; j++)
            #pragma unroll
            for (int h = 0; h < 2; h++)
                #pragma unroll
                for (int q = 0; q < 4; q++) acc[mt][j][h][q] = 0.f;

    #pragma unroll
    for (int p = 0; p < 3; p++) {
        const uint32_t aOff = sb + ((p == 1) ? SA_LO : SA_HI);
        const uint32_t wOff = sb + ((p == 2) ? SW_LO : SW_HI);
        #pragma unroll
        for (int ks = 0; ks < 8; ks++) {
            const uint32_t kb = (uint32_t)(ks * 32);   // 16 bf16 = 32 bytes per k-step
            uint32_t a0[4], a1[4];
            LDSM_X4(a0[0], a0[1], a0[2], a0[3], aOff + aRow0 + kb);
            LDSM_X4(a1[0], a1[1], a1[2], a1[3], aOff + aRow0 + 16 * TSTRIDE + kb);
            uint32_t b[4][4];
            #pragma unroll
            for (int j = 0; j < 4; j++)
                LDSM_X4(b[j][0], b[j][1], b[j][2], b[j][3], wOff + bRow[j] + kb);
            #pragma unroll
            for (int j = 0; j < 4; j++) {
                MMA16816(acc[0][j][0], a0, b[j][0], b[j][1]);
                MMA16816(acc[1][j][0], a1, b[j][0], b[j][1]);
                MMA16816(acc[0][j][1], a0, b[j][2], b[j][3]);
                MMA16816(acc[1][j][1], a1, b[j][2], b[j][3]);
            }
        }
    }

    // ---- epilogue: write fp32 ----
    const int colBase = wn * 64 + (lane & 3) * 2;
    #pragma unroll
    for (int mt = 0; mt < 2; mt++) {
        int row = r0 + wm * 32 + mt * 16 + (lane >> 2);
        #pragma unroll
        for (int j = 0; j < 4; j++)
            #pragma unroll
            for (int h = 0; h < 2; h++) {
                int col = colBase + j * 8 + h * 32;
                if (row < n)
                    *(float2*)&out[(size_t)row * 128 + col] =
                        make_float2(acc[mt][j][h][0], acc[mt][j][h][1]);
                if (row + 8 < n)
                    *(float2*)&out[(size_t)(row + 8) * 128 + col] =
                        make_float2(acc[mt][j][h][2], acc[mt][j][h][3]);
            }
    }
}

// ---------------- GEMM [n,128] x [128,40] (fp32, reads hi/lo activations) ----------------
__global__ __launch_bounds__(320) void gemm40(
    const __nv_bfloat16* __restrict__ Ahi, const __nv_bfloat16* __restrict__ Alo,
    const float* __restrict__ W, float* __restrict__ out, int n)
{
    __shared__ float As[32][128];
    __shared__ float Ws[128 * 40];
    int tid = threadIdx.x;
    int tx = tid % 40;
    int ty = tid / 40;
    int r0 = blockIdx.x * 32;

    for (int idx = tid; idx < 32 * 32; idx += 320) {
        int row = idx >> 5, f = idx & 31;
        int gr = r0 + row;
        float4 v = make_float4(0.f, 0.f, 0.f, 0.f);
        if (gr < n) {
            const __nv_bfloat162* hp = (const __nv_bfloat162*)(Ahi + (size_t)gr * 128 + f * 4);
            const __nv_bfloat162* lp = (const __nv_bfloat162*)(Alo + (size_t)gr * 128 + f * 4);
            __nv_bfloat162 h0 = hp[0], h1 = hp[1], l0 = lp[0], l1 = lp[1];
            v.x = __bfloat162float(h0.x) + __bfloat162float(l0.x);
            v.y = __bfloat162float(h0.y) + __bfloat162float(l0.y);
            v.z = __bfloat162float(h1.x) + __bfloat162float(l1.x);
            v.w = __bfloat162float(h1.y) + __bfloat162float(l1.y);
        }
        *(float4*)&As[row][f * 4] = v;
    }
    for (int idx = tid; idx < 128 * 40; idx += 320) Ws[idx] = W[idx];
    __syncthreads();

    float acc[4] = {0.f, 0.f, 0.f, 0.f};
    #pragma unroll 8
    for (int k = 0; k < 128; k++) {
        float b = Ws[k * 40 + tx];
        #pragma unroll
        for (int i = 0; i < 4; i++) acc[i] += As[ty * 4 + i][k] * b;
    }
    #pragma unroll
    for (int i = 0; i < 4; i++) {
        int gr = r0 + ty * 4 + i;
        if (gr < n) out[gr * 40 + tx] = acc[i];
    }
}

// ---------------- aggregation: warp per node, H=128, emits bf16 hi/lo ----------------
__global__ __launch_bounds__(256) void agg128(
    const float* __restrict__ t, const float* __restrict__ bias,
    __nv_bfloat16* __restrict__ ohi, __nv_bfloat16* __restrict__ olo)
{
    int warp = (blockIdx.x * blockDim.x + threadIdx.x) >> 5;
    if (warp >= N_NODES) return;
    int lane = threadIdx.x & 31;
    const float4* t4 = (const float4*)t;

    float dv = g_dinv[warp];
    float self = dv * dv;
    float4 v = t4[warp * 32 + lane];
    float ax = self * v.x, ay = self * v.y, az = self * v.z, aw = self * v.w;

    int e0 = g_rowptr[warp], e1 = g_rowptr[warp + 1];
    for (int e = e0; e < e1; e++) {
        int s = g_eidx[e];
        float w = g_enorm[e];
        float4 u = t4[s * 32 + lane];
        ax += w * u.x; ay += w * u.y; az += w * u.z; aw += w * u.w;
    }
    float4 bb = ((const float4*)bias)[lane];
    ax = fmaxf(ax + bb.x, 0.f); ay = fmaxf(ay + bb.y, 0.f);
    az = fmaxf(az + bb.z, 0.f); aw = fmaxf(aw + bb.w, 0.f);

    __nv_bfloat16 hx = __float2bfloat16(ax), hy = __float2bfloat16(ay);
    __nv_bfloat16 hz = __float2bfloat16(az), hw = __float2bfloat16(aw);
    __nv_bfloat16 lx = __float2bfloat16(ax - __bfloat162float(hx));
    __nv_bfloat16 ly = __float2bfloat16(ay - __bfloat162float(hy));
    __nv_bfloat16 lz = __float2bfloat16(az - __bfloat162float(hz));
    __nv_bfloat16 lw = __float2bfloat16(aw - __bfloat162float(hw));

    __nv_bfloat162* hp = (__nv_bfloat162*)ohi;
    __nv_bfloat162* lp = (__nv_bfloat162*)olo;
    size_t base = (size_t)warp * 64 + lane * 2;
    __nv_bfloat162 a; a.x = hx; a.y = hy; hp[base] = a;
    __nv_bfloat162 b; b.x = hz; b.y = hw; hp[base + 1] = b;
    __nv_bfloat162 c; c.x = lx; c.y = ly; lp[base] = c;
    __nv_bfloat162 d; d.x = lz; d.y = lw; lp[base + 1] = d;
}

// ---------------- final aggregation (H=40) fused with log_softmax ----------------
__global__ __launch_bounds__(256) void agg40_lsm(
    const float* __restrict__ t, const float* __restrict__ bias,
    float* __restrict__ out)
{
    int warp = (blockIdx.x * blockDim.x + threadIdx.x) >> 5;
    if (warp >= N_NODES) return;
    int lane = threadIdx.x & 31;

    float dv = g_dinv[warp];
    float self = dv * dv;
    bool hi = (lane < 8);
    float a0 = self * t[warp * 40 + lane];
    float a1 = hi ? self * t[warp * 40 + 32 + lane] : 0.f;

    int e0 = g_rowptr[warp], e1 = g_rowptr[warp + 1];
    for (int e = e0; e < e1; e++) {
        int s = g_eidx[e];
        float w = g_enorm[e];
        a0 += w * t[s * 40 + lane];
        if (hi) a1 += w * t[s * 40 + 32 + lane];
    }
    a0 += bias[lane];
    if (hi) a1 += bias[32 + lane];

    float m = fmaxf(a0, hi ? a1 : -INFINITY);
    #pragma unroll
    for (int off = 16; off > 0; off >>= 1)
        m = fmaxf(m, __shfl_xor_sync(0xFFFFFFFFu, m, off));
    float s = expf(a0 - m) + (hi ? expf(a1 - m) : 0.f);
    #pragma unroll
    for (int off = 16; off > 0; off >>= 1)
        s += __shfl_xor_sync(0xFFFFFFFFu, s, off);
    float l = m + logf(s);

    out[warp * 40 + lane] = a0 - l;
    if (hi) out[warp * 40 + 32 + lane] = a1 - l;
}

// ---------------- launch ----------------
extern "C" void kernel_launch(void* const* d_in, const int* in_sizes, int n_in,
                              void* d_out, int out_size)
{
    const float* x  = (const float*)d_in[0];
    const int*   ei = (const int*)d_in[1];
    const float* W1 = (const float*)d_in[2];
    const float* b1 = (const float*)d_in[3];
    const float* W2 = (const float*)d_in[4];
    const float* b2 = (const float*)d_in[5];
    const float* W3 = (const float*)d_in[6];
    const float* b3 = (const float*)d_in[7];
    const float* W4 = (const float*)d_in[8];
    const float* b4 = (const float*)d_in[9];
    float* out = (float*)d_out;

    const int* src = ei;
    const int* dst = ei + N_EDGES;

    float* t;            cudaGetSymbolAddress((void**)&t,   g_t);
    __nv_bfloat16* hi;   cudaGetSymbolAddress((void**)&hi,  g_hi);
    __nv_bfloat16* lo;   cudaGetSymbolAddress((void**)&lo,  g_lo);
    __nv_bfloat16* whi;  cudaGetSymbolAddress((void**)&whi, g_whi);
    __nv_bfloat16* wlo;  cudaGetSymbolAddress((void**)&wlo, g_wlo);

    cudaFuncSetAttribute(gemm_mma, cudaFuncAttributeMaxDynamicSharedMemorySize, SM_TOTAL);

    const int NB_N = (N_NODES + 255) / 256;        // 391
    const int NB_E = (N_EDGES + 255) / 256;        // 2500
    const int NB_TC = (N_NODES + 127) / 128;       // 782
    const int NB_G40 = (N_NODES + 31) / 32;        // 3125
    const int NB_W = (N_NODES * 32 + 255) / 256;   // 12500
    const int NB_S1 = (N_NODES + 1023) / 1024;     // 98
    const int NB_CX = (N_NODES * 32 + 255) / 256;  // 12500

    // graph structure prep
    k_zero<<<NB_N, 256>>>();
    k_count<<<NB_E, 256>>>(dst);
    k_dinv<<<NB_N, 256>>>();
    k_scan1<<<NB_S1, 1024>>>();
    k_scan2<<<1, 128>>>();
    k_scan3<<<NB_N, 256>>>();
    k_scatter<<<NB_E, 256>>>(src, dst);

    // precision-split conversions
    k_convx<<<NB_CX, 256>>>(x);
    k_convw<<<64, 256>>>(W1, whi,             wlo);
    k_convw<<<64, 256>>>(W2, whi + 16384,     wlo + 16384);
    k_convw<<<64, 256>>>(W3, whi + 2 * 16384, wlo + 2 * 16384);

    // layer 1
    gemm_mma<<<NB_TC, 256, SM_TOTAL>>>(hi, lo, whi, wlo, t, N_NODES);
    agg128<<<NB_W, 256>>>(t, b1, hi, lo);
    // layer 2
    gemm_mma<<<NB_TC, 256, SM_TOTAL>>>(hi, lo, whi + 16384, wlo + 16384, t, N_NODES);
    agg128<<<NB_W, 256>>>(t, b2, hi, lo);
    // layer 3
    gemm_mma<<<NB_TC, 256, SM_TOTAL>>>(hi, lo, whi + 2 * 16384, wlo + 2 * 16384, t, N_NODES);
    agg128<<<NB_W, 256>>>(t, b3, hi, lo);
    // layer 4 + log_softmax
    gemm40<<<NB_G40, 320>>>(hi, lo, W4, t, N_NODES);
    agg40_lsm<<<NB_W, 256>>>(t, b4, out);
}